// round 1
// baseline (speedup 1.0000x reference)
#include <cuda_runtime.h>
#include <math.h>

// Problem constants
#define SEQ    2048
#define DM     4096
#define NH     16
#define DH     256
#define RD     64
#define DFF    16384

// Scratch (device globals; no dynamic allocation allowed)
__device__ float g_xn[SEQ * DM];            // 32 MB
__device__ float g_q[SEQ * DM];             // 32 MB
__device__ float g_k[SEQ * DM];             // 32 MB
__device__ float g_v[SEQ * DM];             // 32 MB
__device__ float g_attn[SEQ * DM];          // 32 MB   (attn_vec)
__device__ float g_attnout[SEQ * DM];       // 32 MB   (attn_vec @ wo)
__device__ float g_logits[(size_t)NH * SEQ * SEQ]; // 268 MB (logits -> weights in place)
__device__ float g_ff[(size_t)SEQ * DFF];   // 134 MB  (gelu(xn@w1+b1))

// ---------------------------------------------------------------------------
// LayerNorm: one block per row
// ---------------------------------------------------------------------------
__global__ void ln_kernel(const float* __restrict__ x,
                          const float* __restrict__ scale,
                          const float* __restrict__ offset,
                          float* __restrict__ xn)
{
    __shared__ float red[256];
    int row = blockIdx.x;
    int tid = threadIdx.x;
    const float* xr = x + (size_t)row * DM;
    float* xo = xn + (size_t)row * DM;

    float s = 0.f;
    for (int i = tid; i < DM; i += 256) s += xr[i];
    red[tid] = s; __syncthreads();
    for (int off = 128; off > 0; off >>= 1) {
        if (tid < off) red[tid] += red[tid + off];
        __syncthreads();
    }
    float mean = red[0] / (float)DM;
    __syncthreads();

    float v = 0.f;
    for (int i = tid; i < DM; i += 256) { float d = xr[i] - mean; v += d * d; }
    red[tid] = v; __syncthreads();
    for (int off = 128; off > 0; off >>= 1) {
        if (tid < off) red[tid] += red[tid + off];
        __syncthreads();
    }
    float var = red[0] / (float)DM;
    float r = rsqrtf(var + 1e-5f);

    for (int i = tid; i < DM; i += 256)
        xo[i] = scale[i] * r * (xr[i] - mean) + offset[i];
}

// ---------------------------------------------------------------------------
// RoPE (interleaved pairs on first RD dims of each head), applied to q and k
// Use fp64 sincos to match the numpy-f64 sin/cos table.
// ---------------------------------------------------------------------------
__global__ void rope_kernel(float* __restrict__ q, float* __restrict__ k)
{
    int idx = blockIdx.x * blockDim.x + threadIdx.x; // t*NH*32 + h*32 + i
    if (idx >= SEQ * NH * (RD / 2)) return;
    int i = idx & 31;
    int h = (idx >> 5) & (NH - 1);
    int t = idx >> 9;

    double inv = exp(-(double)i * (log(10000.0) / 32.0));
    double ang = (double)t * inv;
    double ds, dc;
    sincos(ang, &ds, &dc);
    float s = (float)ds, c = (float)dc;

    size_t base = (size_t)t * DM + (size_t)h * DH + 2 * i;
    float q0 = q[base], q1 = q[base + 1];
    q[base]     = q0 * c - q1 * s;
    q[base + 1] = q1 * c + q0 * s;
    float k0 = k[base], k1 = k[base + 1];
    k[base]     = k0 * c - k1 * s;
    k[base + 1] = k1 * c + k0 * s;
}

// ---------------------------------------------------------------------------
// Epilogues
// ---------------------------------------------------------------------------
#define EPI_NONE     0
#define EPI_SCALE    1
#define EPI_GELU     2   // gelu(acc + bias[col])
#define EPI_BIAS_ADD 3   // acc + bias[col] + addv[row,col]

__device__ __forceinline__ float gelu_tanh(float v)
{
    const float c = 0.7978845608028654f;
    float t = tanhf(c * (v + 0.044715f * v * v * v));
    return 0.5f * v * (1.0f + t);
}

// ---------------------------------------------------------------------------
// SGEMM NN: C[M,N] = A[M,K] @ B[K,N]  (128x128 tile, BK=8, 8x8/thread, 256 thr)
// Batched via blockIdx.z with element strides sA/sB/sC.
// Requires: M%128==0, N%128==0, K%8==0, lda/ldb 4-aligned offsets.
// ---------------------------------------------------------------------------
__global__ void sgemm_nn(const float* __restrict__ A, int lda, size_t sA,
                         const float* __restrict__ B, int ldb, size_t sB,
                         float* __restrict__ C, int ldc, size_t sC,
                         int K, int epi,
                         const float* __restrict__ bias,
                         const float* __restrict__ addv,
                         float scale)
{
    __shared__ float As[8][128];
    __shared__ float Bs[8][128];

    A += (size_t)blockIdx.z * sA;
    B += (size_t)blockIdx.z * sB;
    C += (size_t)blockIdx.z * sC;

    int bm = blockIdx.y * 128;
    int bn = blockIdx.x * 128;
    int tid = threadIdx.x;

    int arow = tid >> 1;
    int acol = (tid & 1) << 2;
    int brow = tid >> 5;
    int bcol = (tid & 31) << 2;
    int tx = tid & 15, ty = tid >> 4;

    float acc[8][8];
    #pragma unroll
    for (int i = 0; i < 8; i++)
        #pragma unroll
        for (int j = 0; j < 8; j++) acc[i][j] = 0.f;

    for (int k0 = 0; k0 < K; k0 += 8) {
        float4 av = *(const float4*)(A + (size_t)(bm + arow) * lda + k0 + acol);
        As[acol + 0][arow] = av.x;
        As[acol + 1][arow] = av.y;
        As[acol + 2][arow] = av.z;
        As[acol + 3][arow] = av.w;
        float4 bv = *(const float4*)(B + (size_t)(k0 + brow) * ldb + bn + bcol);
        *(float4*)(&Bs[brow][bcol]) = bv;
        __syncthreads();
        #pragma unroll
        for (int kk = 0; kk < 8; kk++) {
            float ra[8], rb[8];
            #pragma unroll
            for (int i = 0; i < 8; i++) ra[i] = As[kk][ty * 8 + i];
            #pragma unroll
            for (int j = 0; j < 8; j++) rb[j] = Bs[kk][tx * 8 + j];
            #pragma unroll
            for (int i = 0; i < 8; i++)
                #pragma unroll
                for (int j = 0; j < 8; j++) acc[i][j] += ra[i] * rb[j];
        }
        __syncthreads();
    }

    #pragma unroll
    for (int i = 0; i < 8; i++) {
        int row = bm + ty * 8 + i;
        #pragma unroll
        for (int j = 0; j < 8; j++) {
            int col = bn + tx * 8 + j;
            float v = acc[i][j];
            if (epi == EPI_SCALE)          v *= scale;
            else if (epi == EPI_GELU)      v = gelu_tanh(v + bias[col]);
            else if (epi == EPI_BIAS_ADD)  v += bias[col] + addv[(size_t)row * ldc + col];
            C[(size_t)row * ldc + col] = v;
        }
    }
}

// ---------------------------------------------------------------------------
// SGEMM NT: C[M,N] = A[M,K] @ B^T where B is [N,K] row-major. Same tiling.
// ---------------------------------------------------------------------------
__global__ void sgemm_nt(const float* __restrict__ A, int lda, size_t sA,
                         const float* __restrict__ B, int ldb, size_t sB,
                         float* __restrict__ C, int ldc, size_t sC,
                         int K, int epi, float scale)
{
    __shared__ float As[8][128];
    __shared__ float Bs[8][128];

    A += (size_t)blockIdx.z * sA;
    B += (size_t)blockIdx.z * sB;
    C += (size_t)blockIdx.z * sC;

    int bm = blockIdx.y * 128;
    int bn = blockIdx.x * 128;
    int tid = threadIdx.x;

    int arow = tid >> 1;
    int acol = (tid & 1) << 2;
    int tx = tid & 15, ty = tid >> 4;

    float acc[8][8];
    #pragma unroll
    for (int i = 0; i < 8; i++)
        #pragma unroll
        for (int j = 0; j < 8; j++) acc[i][j] = 0.f;

    for (int k0 = 0; k0 < K; k0 += 8) {
        float4 av = *(const float4*)(A + (size_t)(bm + arow) * lda + k0 + acol);
        As[acol + 0][arow] = av.x;
        As[acol + 1][arow] = av.y;
        As[acol + 2][arow] = av.z;
        As[acol + 3][arow] = av.w;
        // B tile: Bs[kk][n] = B[(bn+n)*ldb + k0+kk]
        float4 bv = *(const float4*)(B + (size_t)(bn + arow) * ldb + k0 + acol);
        Bs[acol + 0][arow] = bv.x;
        Bs[acol + 1][arow] = bv.y;
        Bs[acol + 2][arow] = bv.z;
        Bs[acol + 3][arow] = bv.w;
        __syncthreads();
        #pragma unroll
        for (int kk = 0; kk < 8; kk++) {
            float ra[8], rb[8];
            #pragma unroll
            for (int i = 0; i < 8; i++) ra[i] = As[kk][ty * 8 + i];
            #pragma unroll
            for (int j = 0; j < 8; j++) rb[j] = Bs[kk][tx * 8 + j];
            #pragma unroll
            for (int i = 0; i < 8; i++)
                #pragma unroll
                for (int j = 0; j < 8; j++) acc[i][j] += ra[i] * rb[j];
        }
        __syncthreads();
    }

    #pragma unroll
    for (int i = 0; i < 8; i++) {
        int row = bm + ty * 8 + i;
        #pragma unroll
        for (int j = 0; j < 8; j++) {
            int col = bn + tx * 8 + j;
            float v = acc[i][j];
            if (epi == EPI_SCALE) v *= scale;
            C[(size_t)row * ldc + col] = v;
        }
    }
}

// ---------------------------------------------------------------------------
// Causal softmax, in place on logits (one block per (t, h))
// weights[h,t,T] = softmax_T<=t( logits + attn_bias[t,T] ), 0 for T>t
// ---------------------------------------------------------------------------
__global__ void softmax_kernel(float* __restrict__ logits,
                               const float* __restrict__ attn_bias)
{
    __shared__ float red[256];
    int t = blockIdx.x;
    int h = blockIdx.y;
    int tid = threadIdx.x;
    size_t base = ((size_t)h * SEQ + t) * SEQ;
    const float* brow = attn_bias + (size_t)t * SEQ;

    // pass 1: max
    float m = -INFINITY;
    for (int T = tid; T <= t; T += 256) {
        float l = logits[base + T] + brow[T];
        m = fmaxf(m, l);
    }
    red[tid] = m; __syncthreads();
    for (int off = 128; off > 0; off >>= 1) {
        if (tid < off) red[tid] = fmaxf(red[tid], red[tid + off]);
        __syncthreads();
    }
    m = red[0]; __syncthreads();

    // pass 2: exp + sum (write exp in place)
    float s = 0.f;
    for (int T = tid; T <= t; T += 256) {
        float e = expf(logits[base + T] + brow[T] - m);
        logits[base + T] = e;
        s += e;
    }
    red[tid] = s; __syncthreads();
    for (int off = 128; off > 0; off >>= 1) {
        if (tid < off) red[tid] += red[tid + off];
        __syncthreads();
    }
    float inv = 1.0f / red[0];

    // pass 3: normalize + zero tail
    for (int T = tid; T <= t; T += 256)
        logits[base + T] *= inv;
    for (int T = t + 1 + tid; T < SEQ; T += 256)
        logits[base + T] = 0.f;
}

// ---------------------------------------------------------------------------
// Launcher
// ---------------------------------------------------------------------------
extern "C" void kernel_launch(void* const* d_in, const int* in_sizes, int n_in,
                              void* d_out, int out_size)
{
    const float* x         = (const float*)d_in[0];
    const float* attn_bias = (const float*)d_in[1];
    const float* ln_scale  = (const float*)d_in[2];
    const float* ln_offset = (const float*)d_in[3];
    const float* wq        = (const float*)d_in[4];
    const float* wk        = (const float*)d_in[5];
    const float* wv        = (const float*)d_in[6];
    const float* wo        = (const float*)d_in[7];
    const float* w1        = (const float*)d_in[8];
    const float* b1        = (const float*)d_in[9];
    const float* w2        = (const float*)d_in[10];
    const float* b2        = (const float*)d_in[11];
    float* out = (float*)d_out;

    float *xn, *q, *k, *v, *attn, *attnout, *logits, *ff;
    cudaGetSymbolAddress((void**)&xn,      g_xn);
    cudaGetSymbolAddress((void**)&q,       g_q);
    cudaGetSymbolAddress((void**)&k,       g_k);
    cudaGetSymbolAddress((void**)&v,       g_v);
    cudaGetSymbolAddress((void**)&attn,    g_attn);
    cudaGetSymbolAddress((void**)&attnout, g_attnout);
    cudaGetSymbolAddress((void**)&logits,  g_logits);
    cudaGetSymbolAddress((void**)&ff,      g_ff);

    // 1. LayerNorm
    ln_kernel<<<SEQ, 256>>>(x, ln_scale, ln_offset, xn);

    // 2. Q,K,V projections: [2048,4096] @ [4096,4096]
    dim3 gProj(DM / 128, SEQ / 128, 1);
    sgemm_nn<<<gProj, 256>>>(xn, DM, 0, wq, DM, 0, q, DM, 0, DM, EPI_NONE, nullptr, nullptr, 1.f);
    sgemm_nn<<<gProj, 256>>>(xn, DM, 0, wk, DM, 0, k, DM, 0, DM, EPI_NONE, nullptr, nullptr, 1.f);
    sgemm_nn<<<gProj, 256>>>(xn, DM, 0, wv, DM, 0, v, DM, 0, DM, EPI_NONE, nullptr, nullptr, 1.f);

    // 3. RoPE on q,k
    int rope_n = SEQ * NH * (RD / 2);
    rope_kernel<<<(rope_n + 255) / 256, 256>>>(q, k);

    // 4. logits[h] = (q_h @ k_h^T) / 16, batched over heads (NT GEMM)
    dim3 gLog(SEQ / 128, SEQ / 128, NH);
    sgemm_nt<<<gLog, 256>>>(q, DM, DH, k, DM, DH,
                            logits, SEQ, (size_t)SEQ * SEQ,
                            DH, EPI_SCALE, 0.0625f);

    // 5. causal softmax (in place)
    dim3 gSm(SEQ, NH, 1);
    softmax_kernel<<<gSm, 256>>>(logits, attn_bias);

    // 6. attn_vec[h] = weights_h @ v_h   (M=2048, N=256, K=2048)
    dim3 gAV(DH / 128, SEQ / 128, NH);
    sgemm_nn<<<gAV, 256>>>(logits, SEQ, (size_t)SEQ * SEQ,
                           v, DM, DH,
                           attn, DM, DH,
                           SEQ, EPI_NONE, nullptr, nullptr, 1.f);

    // 7. attn_out = attn_vec @ wo
    sgemm_nn<<<gProj, 256>>>(attn, DM, 0, wo, DM, 0, attnout, DM, 0, DM,
                             EPI_NONE, nullptr, nullptr, 1.f);

    // 8. ff = gelu(xn @ w1 + b1)   (N=16384)
    dim3 gFF1(DFF / 128, SEQ / 128, 1);
    sgemm_nn<<<gFF1, 256>>>(xn, DM, 0, w1, DFF, 0, ff, DFF, 0, DM,
                            EPI_GELU, b1, nullptr, 1.f);

    // 9. out = ff @ w2 + b2 + attn_out
    dim3 gFF2(DM / 128, SEQ / 128, 1);
    sgemm_nn<<<gFF2, 256>>>(ff, DFF, 0, w2, DM, 0, out, DM, 0, DFF,
                            EPI_BIAS_ADD, b2, attnout, 1.f);
}

// round 3
// speedup vs baseline: 3.4548x; 3.4548x over previous
#include <cuda_runtime.h>
#include <cuda_bf16.h>
#include <math.h>
#include <stdint.h>

typedef __nv_bfloat16 bf16;

#define SEQ 2048
#define DM  4096
#define NH  16
#define DH  256
#define DFF 16384

// GEMM tiling: CTA 128x128, BK=64, 8 warps (2x4), warp tile 64x32
#define BM 128
#define BN 128
#define BK 64
#define TILE_B   16384               // one 128x128-byte operand tile
#define BUF_B    (4 * TILE_B)        // A hi/lo + B hi/lo = 64KB
#define GEMM_SMEM (2 * BUF_B)        // 128KB double-buffered

// ---------------------------------------------------------------------------
// Device-global scratch
// ---------------------------------------------------------------------------
__device__ bf16 g_xnh[SEQ*DM], g_xnl[SEQ*DM];
__device__ float g_q[SEQ*DM], g_k[SEQ*DM], g_v[SEQ*DM];
__device__ bf16 g_qh[SEQ*DM], g_ql[SEQ*DM], g_kh[SEQ*DM], g_kl[SEQ*DM];
__device__ bf16 g_vth[(size_t)DM*SEQ], g_vtl[(size_t)DM*SEQ];
__device__ float g_logits[(size_t)NH*SEQ*SEQ];
__device__ bf16 g_wgh[(size_t)NH*SEQ*SEQ], g_wgl[(size_t)NH*SEQ*SEQ];
__device__ bf16 g_avh[SEQ*DM], g_avl[SEQ*DM];
__device__ float g_attnout[SEQ*DM];
__device__ bf16 g_ffh[(size_t)SEQ*DFF], g_ffl[(size_t)SEQ*DFF];
__device__ bf16 g_wqth[(size_t)DM*DM],  g_wqtl[(size_t)DM*DM];
__device__ bf16 g_wkth[(size_t)DM*DM],  g_wktl[(size_t)DM*DM];
__device__ bf16 g_wvth[(size_t)DM*DM],  g_wvtl[(size_t)DM*DM];
__device__ bf16 g_woth[(size_t)DM*DM],  g_wotl[(size_t)DM*DM];
__device__ bf16 g_w1th[(size_t)DFF*DM], g_w1tl[(size_t)DFF*DM];
__device__ bf16 g_w2th[(size_t)DM*DFF], g_w2tl[(size_t)DM*DFF];

// ---------------------------------------------------------------------------
// PTX helpers (baseline ISA only: cp.async, ldmatrix, mma.sync)
// ---------------------------------------------------------------------------
__device__ __forceinline__ uint32_t smem_u32(const void* p) {
    uint32_t r;
    asm("{ .reg .u64 t; cvta.to.shared.u64 t, %1; cvt.u32.u64 %0, t; }" : "=r"(r) : "l"(p));
    return r;
}
__device__ __forceinline__ void cp16(uint32_t dst, const void* src) {
    asm volatile("cp.async.cg.shared.global [%0], [%1], 16;" :: "r"(dst), "l"(src));
}
#define CP_COMMIT() asm volatile("cp.async.commit_group;")
#define CP_WAIT(n)  asm volatile("cp.async.wait_group %0;" :: "n"(n))

#define LDMX4(r, a) \
    asm volatile("ldmatrix.sync.aligned.m8n8.x4.shared.b16 {%0,%1,%2,%3}, [%4];" \
        : "=r"((r)[0]), "=r"((r)[1]), "=r"((r)[2]), "=r"((r)[3]) : "r"(a))

#define MMA16816(c, a, b) \
    asm volatile("mma.sync.aligned.m16n8k16.row.col.f32.bf16.bf16.f32 " \
        "{%0,%1,%2,%3}, {%4,%5,%6,%7}, {%8,%9}, {%0,%1,%2,%3};" \
        : "+f"((c)[0]), "+f"((c)[1]), "+f"((c)[2]), "+f"((c)[3]) \
        : "r"((a)[0]), "r"((a)[1]), "r"((a)[2]), "r"((a)[3]), \
          "r"((b)[0]), "r"((b)[1]))

__device__ __forceinline__ void split_store(float v, bf16* ph, bf16* pl, size_t idx) {
    bf16 h = __float2bfloat16(v);
    ph[idx] = h;
    pl[idx] = __float2bfloat16(v - __bfloat162float(h));
}

// ---------------------------------------------------------------------------
// Epilogue codes
// ---------------------------------------------------------------------------
#define EPI_F32       0
#define EPI_SCALE     1
#define EPI_HILO      2
#define EPI_GELU_HILO 3
#define EPI_BIAS_ADD  4

__device__ __forceinline__ float gelu_tanh(float v) {
    const float c = 0.7978845608028654f;
    float t = tanhf(c * (v + 0.044715f * v * v * v));
    return 0.5f * v * (1.0f + t);
}

// ---------------------------------------------------------------------------
// Split-bf16 tensor-core GEMM: C[M,N] = A @ B^T
// A[M,K] row-major hi/lo bf16; B[N,K] row-major hi/lo bf16; fp32 accumulate.
// ---------------------------------------------------------------------------
__global__ void __launch_bounds__(256, 1) gemm_bf16x3(
    const bf16* __restrict__ Ah, const bf16* __restrict__ Al, int lda, unsigned long long sA,
    const bf16* __restrict__ Bh, const bf16* __restrict__ Bl, int ldb, unsigned long long sB,
    int K, int epi,
    float* __restrict__ Cf, bf16* __restrict__ Ch, bf16* __restrict__ Cl,
    int ldc, unsigned long long sC,
    const float* __restrict__ bias, const float* __restrict__ addv, float scale)
{
    extern __shared__ char smem[];
    uint32_t sb = smem_u32(smem);
    int tid = threadIdx.x;
    int wid = tid >> 5, lane = tid & 31;
    int warp_m = wid >> 2, warp_n = wid & 3;

    Ah += (size_t)blockIdx.z * sA;  Al += (size_t)blockIdx.z * sA;
    Bh += (size_t)blockIdx.z * sB;  Bl += (size_t)blockIdx.z * sB;
    size_t coff = (size_t)blockIdx.z * sC;

    int bm = blockIdx.y * BM;
    int bn = blockIdx.x * BN;

    // ldmatrix per-lane geometry
    int a_r  = ((lane >> 3) & 1) * 8 + (lane & 7);  // row within 16-row tile
    int a_cb = (lane >> 4) * 16;                    // k-byte sub-offset
    int b_r  = (lane >> 4) * 8 + (lane & 7);        // n-row within 16-row pair
    int b_cb = ((lane >> 3) & 1) * 16;

    float acc[4][4][4];
    #pragma unroll
    for (int i = 0; i < 4; i++)
        #pragma unroll
        for (int j = 0; j < 4; j++)
            #pragma unroll
            for (int e = 0; e < 4; e++) acc[i][j][e] = 0.f;

    // Fill macro: A hi/lo + B hi/lo tiles (BM==BN==128 rows x 128B, SW128)
#define LOAD_CHUNK(k0, bufb) do {                                              \
        _Pragma("unroll")                                                      \
        for (int t = 0; t < 4; t++) {                                          \
            int ch = tid + t * 256;                                            \
            int row = ch >> 3, c = ch & 7;                                     \
            uint32_t off = row * 128 + ((c * 16) ^ ((row * 16) & 0x70));       \
            const bf16* pah = Ah + (size_t)(bm + row) * lda + (k0) + c * 8;    \
            const bf16* pal = Al + (size_t)(bm + row) * lda + (k0) + c * 8;    \
            const bf16* pbh = Bh + (size_t)(bn + row) * ldb + (k0) + c * 8;    \
            const bf16* pbl = Bl + (size_t)(bn + row) * ldb + (k0) + c * 8;    \
            cp16((bufb) + off,             pah);                               \
            cp16((bufb) + TILE_B + off,    pal);                               \
            cp16((bufb) + 2*TILE_B + off,  pbh);                               \
            cp16((bufb) + 3*TILE_B + off,  pbl);                               \
        }                                                                      \
    } while (0)

    int nk = K / BK;
    LOAD_CHUNK(0, sb);
    CP_COMMIT();

    for (int i = 0; i < nk; i++) {
        uint32_t bufb = sb + (uint32_t)(i & 1) * BUF_B;
        if (i + 1 < nk) {
            uint32_t nb = sb + (uint32_t)((i + 1) & 1) * BUF_B;
            LOAD_CHUNK((i + 1) * BK, nb);
            CP_COMMIT();
            CP_WAIT(1);
        } else {
            CP_WAIT(0);
        }
        __syncthreads();

        #pragma unroll
        for (int ks = 0; ks < 4; ks++) {
            uint32_t ahf[4][4], alf[4][4];
            #pragma unroll
            for (int mt = 0; mt < 4; mt++) {
                int row = warp_m * 64 + mt * 16 + a_r;
                uint32_t cb = ks * 32 + a_cb;
                uint32_t off = row * 128 + (cb ^ ((row * 16) & 0x70));
                LDMX4(ahf[mt], bufb + off);
                LDMX4(alf[mt], bufb + TILE_B + off);
            }
            uint32_t bhf[4][2], blf[4][2];
            #pragma unroll
            for (int p = 0; p < 2; p++) {
                int row = warp_n * 32 + p * 16 + b_r;
                uint32_t cb = ks * 32 + b_cb;
                uint32_t off = row * 128 + (cb ^ ((row * 16) & 0x70));
                uint32_t r[4];
                LDMX4(r, bufb + 2 * TILE_B + off);
                bhf[2*p][0] = r[0]; bhf[2*p][1] = r[1];
                bhf[2*p+1][0] = r[2]; bhf[2*p+1][1] = r[3];
                LDMX4(r, bufb + 3 * TILE_B + off);
                blf[2*p][0] = r[0]; blf[2*p][1] = r[1];
                blf[2*p+1][0] = r[2]; blf[2*p+1][1] = r[3];
            }
            #pragma unroll
            for (int mt = 0; mt < 4; mt++)
                #pragma unroll
                for (int nt = 0; nt < 4; nt++) {
                    MMA16816(acc[mt][nt], ahf[mt], bhf[nt]);
                    MMA16816(acc[mt][nt], ahf[mt], blf[nt]);
                    MMA16816(acc[mt][nt], alf[mt], bhf[nt]);
                }
        }
        __syncthreads();
    }
#undef LOAD_CHUNK

    // Epilogue: direct global stores
    int g = lane >> 2, tg = lane & 3;
    #pragma unroll
    for (int mt = 0; mt < 4; mt++) {
        #pragma unroll
        for (int nt = 0; nt < 4; nt++) {
            int row0 = bm + warp_m * 64 + mt * 16 + g;
            int col  = bn + warp_n * 32 + nt * 8 + tg * 2;
            float* a = acc[mt][nt];
            #pragma unroll
            for (int half = 0; half < 2; half++) {
                int row = row0 + half * 8;
                float v0 = a[half * 2 + 0], v1 = a[half * 2 + 1];
                size_t idx = coff + (size_t)row * ldc + col;
                if (epi == EPI_F32) {
                    *(float2*)(Cf + idx) = make_float2(v0, v1);
                } else if (epi == EPI_SCALE) {
                    *(float2*)(Cf + idx) = make_float2(v0 * scale, v1 * scale);
                } else if (epi == EPI_HILO) {
                    bf16 h0 = __float2bfloat16(v0), h1 = __float2bfloat16(v1);
                    __nv_bfloat162 hp; hp.x = h0; hp.y = h1;
                    __nv_bfloat162 lp;
                    lp.x = __float2bfloat16(v0 - __bfloat162float(h0));
                    lp.y = __float2bfloat16(v1 - __bfloat162float(h1));
                    *(__nv_bfloat162*)(Ch + idx) = hp;
                    *(__nv_bfloat162*)(Cl + idx) = lp;
                } else if (epi == EPI_GELU_HILO) {
                    float g0 = gelu_tanh(v0 + bias[col]);
                    float g1 = gelu_tanh(v1 + bias[col + 1]);
                    bf16 h0 = __float2bfloat16(g0), h1 = __float2bfloat16(g1);
                    __nv_bfloat162 hp; hp.x = h0; hp.y = h1;
                    __nv_bfloat162 lp;
                    lp.x = __float2bfloat16(g0 - __bfloat162float(h0));
                    lp.y = __float2bfloat16(g1 - __bfloat162float(h1));
                    *(__nv_bfloat162*)(Ch + idx) = hp;
                    *(__nv_bfloat162*)(Cl + idx) = lp;
                } else { // EPI_BIAS_ADD
                    float2 av = *(const float2*)(addv + idx);
                    *(float2*)(Cf + idx) = make_float2(v0 + bias[col] + av.x,
                                                       v1 + bias[col + 1] + av.y);
                }
            }
        }
    }
}

// ---------------------------------------------------------------------------
// LayerNorm -> hi/lo bf16
// ---------------------------------------------------------------------------
__global__ void ln_kernel(const float* __restrict__ x,
                          const float* __restrict__ scale,
                          const float* __restrict__ offset,
                          bf16* __restrict__ xh, bf16* __restrict__ xl)
{
    __shared__ float red[256];
    int row = blockIdx.x;
    int tid = threadIdx.x;
    const float* xr = x + (size_t)row * DM;

    float s = 0.f;
    for (int i = tid; i < DM; i += 256) s += xr[i];
    red[tid] = s; __syncthreads();
    for (int o = 128; o > 0; o >>= 1) { if (tid < o) red[tid] += red[tid + o]; __syncthreads(); }
    float mean = red[0] / (float)DM;
    __syncthreads();

    float v = 0.f;
    for (int i = tid; i < DM; i += 256) { float d = xr[i] - mean; v += d * d; }
    red[tid] = v; __syncthreads();
    for (int o = 128; o > 0; o >>= 1) { if (tid < o) red[tid] += red[tid + o]; __syncthreads(); }
    float r = rsqrtf(red[0] / (float)DM + 1e-5f);

    for (int i = tid; i < DM; i += 256) {
        float y = scale[i] * r * (xr[i] - mean) + offset[i];
        split_store(y, xh, xl, (size_t)row * DM + i);
    }
}

// ---------------------------------------------------------------------------
// Transpose + hi/lo convert: in[R][C] fp32 -> out[C][R] hi/lo bf16
// ---------------------------------------------------------------------------
__global__ void transcvt_kernel(const float* __restrict__ in, int R, int C,
                                bf16* __restrict__ oh, bf16* __restrict__ ol)
{
    __shared__ float t[32][33];
    int c0 = blockIdx.x * 32;
    int r0 = blockIdx.y * 32;
    int tx = threadIdx.x, ty = threadIdx.y;  // (32,8)
    #pragma unroll
    for (int j = 0; j < 32; j += 8)
        t[ty + j][tx] = in[(size_t)(r0 + ty + j) * C + c0 + tx];
    __syncthreads();
    #pragma unroll
    for (int j = 0; j < 32; j += 8) {
        float v = t[tx][ty + j];
        split_store(v, oh, ol, (size_t)(c0 + ty + j) * R + r0 + tx);
    }
}

// ---------------------------------------------------------------------------
// RoPE (fp64 angles, first 64 dims per head) + hi/lo convert of full q,k
// ---------------------------------------------------------------------------
__global__ void rope_cvt_kernel(const float* __restrict__ q, const float* __restrict__ k,
                                bf16* __restrict__ qh, bf16* __restrict__ ql,
                                bf16* __restrict__ kh, bf16* __restrict__ kl)
{
    int idx = blockIdx.x * 256 + threadIdx.x;   // SEQ*NH*128 pairs
    if (idx >= SEQ * NH * 128) return;
    int p = idx & 127;
    int h = (idx >> 7) & (NH - 1);
    int t = idx >> 11;
    size_t base = (size_t)t * DM + (size_t)h * DH + 2 * p;
    float q0 = q[base], q1 = q[base + 1];
    float k0 = k[base], k1 = k[base + 1];
    if (p < 32) {
        double inv = exp(-(double)p * (9.210340371976184 / 32.0));
        double ds, dc;
        sincos((double)t * inv, &ds, &dc);
        float s = (float)ds, c = (float)dc;
        float a = q0 * c - q1 * s, b = q1 * c + q0 * s; q0 = a; q1 = b;
        a = k0 * c - k1 * s; b = k1 * c + k0 * s; k0 = a; k1 = b;
    }
    split_store(q0, qh, ql, base);
    split_store(q1, qh, ql, base + 1);
    split_store(k0, kh, kl, base);
    split_store(k1, kh, kl, base + 1);
}

// ---------------------------------------------------------------------------
// Causal softmax -> hi/lo bf16 weights, zero tail
// ---------------------------------------------------------------------------
__global__ void softmax_kernel(const float* __restrict__ logits,
                               const float* __restrict__ attn_bias,
                               bf16* __restrict__ wh, bf16* __restrict__ wl)
{
    __shared__ float red[256];
    int t = blockIdx.x;
    int h = blockIdx.y;
    int tid = threadIdx.x;
    size_t base = ((size_t)h * SEQ + t) * SEQ;
    const float* brow = attn_bias + (size_t)t * SEQ;

    float m = -INFINITY;
    for (int T = tid; T <= t; T += 256) m = fmaxf(m, logits[base + T] + brow[T]);
    red[tid] = m; __syncthreads();
    for (int o = 128; o > 0; o >>= 1) { if (tid < o) red[tid] = fmaxf(red[tid], red[tid + o]); __syncthreads(); }
    m = red[0]; __syncthreads();

    float s = 0.f;
    for (int T = tid; T <= t; T += 256) s += expf(logits[base + T] + brow[T] - m);
    red[tid] = s; __syncthreads();
    for (int o = 128; o > 0; o >>= 1) { if (tid < o) red[tid] += red[tid + o]; __syncthreads(); }
    float inv = 1.0f / red[0];

    for (int T = tid; T <= t; T += 256) {
        float p = expf(logits[base + T] + brow[T] - m) * inv;
        split_store(p, wh, wl, base + T);
    }
    for (int T = t + 1 + tid; T < SEQ; T += 256) {
        wh[base + T] = __float2bfloat16(0.f);
        wl[base + T] = __float2bfloat16(0.f);
    }
}

// ---------------------------------------------------------------------------
// Launcher
// ---------------------------------------------------------------------------
extern "C" void kernel_launch(void* const* d_in, const int* in_sizes, int n_in,
                              void* d_out, int out_size)
{
    const float* x         = (const float*)d_in[0];
    const float* attn_bias = (const float*)d_in[1];
    const float* ln_scale  = (const float*)d_in[2];
    const float* ln_offset = (const float*)d_in[3];
    const float* wq        = (const float*)d_in[4];
    const float* wk        = (const float*)d_in[5];
    const float* wv        = (const float*)d_in[6];
    const float* wo        = (const float*)d_in[7];
    const float* w1        = (const float*)d_in[8];
    const float* b1        = (const float*)d_in[9];
    const float* w2        = (const float*)d_in[10];
    const float* b2        = (const float*)d_in[11];
    float* out = (float*)d_out;

    cudaFuncSetAttribute(gemm_bf16x3, cudaFuncAttributeMaxDynamicSharedMemorySize, GEMM_SMEM);

    bf16 *xnh, *xnl, *qh, *ql, *kh, *kl, *vth, *vtl, *wgh, *wgl, *avh, *avl, *ffh, *ffl;
    bf16 *wqth, *wqtl, *wkth, *wktl, *wvth, *wvtl, *woth, *wotl, *w1th, *w1tl, *w2th, *w2tl;
    float *q, *k, *v, *logits, *attnout;
    cudaGetSymbolAddress((void**)&xnh, g_xnh);   cudaGetSymbolAddress((void**)&xnl, g_xnl);
    cudaGetSymbolAddress((void**)&q, g_q);       cudaGetSymbolAddress((void**)&k, g_k);
    cudaGetSymbolAddress((void**)&v, g_v);
    cudaGetSymbolAddress((void**)&qh, g_qh);     cudaGetSymbolAddress((void**)&ql, g_ql);
    cudaGetSymbolAddress((void**)&kh, g_kh);     cudaGetSymbolAddress((void**)&kl, g_kl);
    cudaGetSymbolAddress((void**)&vth, g_vth);   cudaGetSymbolAddress((void**)&vtl, g_vtl);
    cudaGetSymbolAddress((void**)&logits, g_logits);
    cudaGetSymbolAddress((void**)&wgh, g_wgh);   cudaGetSymbolAddress((void**)&wgl, g_wgl);
    cudaGetSymbolAddress((void**)&avh, g_avh);   cudaGetSymbolAddress((void**)&avl, g_avl);
    cudaGetSymbolAddress((void**)&attnout, g_attnout);
    cudaGetSymbolAddress((void**)&ffh, g_ffh);   cudaGetSymbolAddress((void**)&ffl, g_ffl);
    cudaGetSymbolAddress((void**)&wqth, g_wqth); cudaGetSymbolAddress((void**)&wqtl, g_wqtl);
    cudaGetSymbolAddress((void**)&wkth, g_wkth); cudaGetSymbolAddress((void**)&wktl, g_wktl);
    cudaGetSymbolAddress((void**)&wvth, g_wvth); cudaGetSymbolAddress((void**)&wvtl, g_wvtl);
    cudaGetSymbolAddress((void**)&woth, g_woth); cudaGetSymbolAddress((void**)&wotl, g_wotl);
    cudaGetSymbolAddress((void**)&w1th, g_w1th); cudaGetSymbolAddress((void**)&w1tl, g_w1tl);
    cudaGetSymbolAddress((void**)&w2th, g_w2th); cudaGetSymbolAddress((void**)&w2tl, g_w2tl);

    dim3 tb(32, 8);
    // weight prep: W[K][N] fp32 -> Wt[N][K] hi/lo bf16
    transcvt_kernel<<<dim3(DM / 32, DM / 32), tb>>>(wq, DM, DM, wqth, wqtl);
    transcvt_kernel<<<dim3(DM / 32, DM / 32), tb>>>(wk, DM, DM, wkth, wktl);
    transcvt_kernel<<<dim3(DM / 32, DM / 32), tb>>>(wv, DM, DM, wvth, wvtl);
    transcvt_kernel<<<dim3(DM / 32, DM / 32), tb>>>(wo, DM, DM, woth, wotl);
    transcvt_kernel<<<dim3(DFF / 32, DM / 32), tb>>>(w1, DM, DFF, w1th, w1tl);
    transcvt_kernel<<<dim3(DM / 32, DFF / 32), tb>>>(w2, DFF, DM, w2th, w2tl);

    // LayerNorm
    ln_kernel<<<SEQ, 256>>>(x, ln_scale, ln_offset, xnh, xnl);

    // QKV projections (fp32 out for rope / v-transpose)
    dim3 gProj(DM / BN, SEQ / BM, 1);
    gemm_bf16x3<<<gProj, 256, GEMM_SMEM>>>(xnh, xnl, DM, 0, wqth, wqtl, DM, 0, DM,
                                           EPI_F32, q, nullptr, nullptr, DM, 0, nullptr, nullptr, 1.f);
    gemm_bf16x3<<<gProj, 256, GEMM_SMEM>>>(xnh, xnl, DM, 0, wkth, wktl, DM, 0, DM,
                                           EPI_F32, k, nullptr, nullptr, DM, 0, nullptr, nullptr, 1.f);
    gemm_bf16x3<<<gProj, 256, GEMM_SMEM>>>(xnh, xnl, DM, 0, wvth, wvtl, DM, 0, DM,
                                           EPI_F32, v, nullptr, nullptr, DM, 0, nullptr, nullptr, 1.f);

    // RoPE + q/k hi/lo convert
    rope_cvt_kernel<<<(SEQ * NH * 128 + 255) / 256, 256>>>(q, k, qh, ql, kh, kl);

    // v transpose: v[SEQ][DM] -> vt[DM][SEQ] hi/lo
    transcvt_kernel<<<dim3(DM / 32, SEQ / 32), tb>>>(v, SEQ, DM, vth, vtl);

    // logits[h] = q_h @ k_h^T / 16
    dim3 gLog(SEQ / BN, SEQ / BM, NH);
    gemm_bf16x3<<<gLog, 256, GEMM_SMEM>>>(qh, ql, DM, DH, kh, kl, DM, DH, DH,
                                          EPI_SCALE, logits, nullptr, nullptr, SEQ, (unsigned long long)SEQ * SEQ,
                                          nullptr, nullptr, 0.0625f);

    // softmax -> W hi/lo
    softmax_kernel<<<dim3(SEQ, NH), 256>>>(logits, attn_bias, wgh, wgl);

    // attn_vec[h] = W_h @ v_h   (N=256 per head)
    dim3 gAV(DH / BN, SEQ / BM, NH);
    gemm_bf16x3<<<gAV, 256, GEMM_SMEM>>>(wgh, wgl, SEQ, (unsigned long long)SEQ * SEQ,
                                         vth, vtl, SEQ, (unsigned long long)DH * SEQ, SEQ,
                                         EPI_HILO, nullptr, avh, avl, DM, DH, nullptr, nullptr, 1.f);

    // attn_out = attn_vec @ wo
    gemm_bf16x3<<<gProj, 256, GEMM_SMEM>>>(avh, avl, DM, 0, woth, wotl, DM, 0, DM,
                                           EPI_F32, attnout, nullptr, nullptr, DM, 0, nullptr, nullptr, 1.f);

    // ff = gelu(xn @ w1 + b1) -> hi/lo
    dim3 gFF1(DFF / BN, SEQ / BM, 1);
    gemm_bf16x3<<<gFF1, 256, GEMM_SMEM>>>(xnh, xnl, DM, 0, w1th, w1tl, DM, 0, DM,
                                          EPI_GELU_HILO, nullptr, ffh, ffl, DFF, 0, b1, nullptr, 1.f);

    // out = ff @ w2 + b2 + attn_out
    dim3 gFF2(DM / BN, SEQ / BM, 1);
    gemm_bf16x3<<<gFF2, 256, GEMM_SMEM>>>(ffh, ffl, DFF, 0, w2th, w2tl, DFF, 0, DFF,
                                          EPI_BIAS_ADD, out, nullptr, nullptr, DM, 0, b2, attnout, 1.f);
}

// round 4
// speedup vs baseline: 3.6731x; 1.0632x over previous
#include <cuda_runtime.h>
#include <cuda_bf16.h>
#include <math.h>
#include <stdint.h>

typedef __nv_bfloat16 bf16;

#define SEQ 2048
#define DM  4096
#define NH  16
#define DH  256
#define DFF 16384

// GEMM tiling: CTA 128x256, BK=64, 8 warps (2x4), warp tile 64x64
#define BM 128
#define BN 256
#define BK 64
#define A_TILE_B 16384               // 128 rows x 128B
#define B_TILE_B 32768               // 256 rows x 128B
#define BUF_B    (2 * A_TILE_B + 2 * B_TILE_B)   // 96KB
#define GEMM_SMEM (2 * BUF_B)                    // 192KB

// ---------------------------------------------------------------------------
// Device-global scratch
// ---------------------------------------------------------------------------
__device__ bf16 g_xnh[SEQ*DM], g_xnl[SEQ*DM];
__device__ float g_q[SEQ*DM], g_k[SEQ*DM], g_v[SEQ*DM];
__device__ bf16 g_qh[SEQ*DM], g_ql[SEQ*DM], g_kh[SEQ*DM], g_kl[SEQ*DM];
__device__ bf16 g_vth[(size_t)DM*SEQ], g_vtl[(size_t)DM*SEQ];
__device__ float g_logits[(size_t)NH*SEQ*SEQ];
__device__ bf16 g_wgh[(size_t)NH*SEQ*SEQ], g_wgl[(size_t)NH*SEQ*SEQ];
__device__ bf16 g_avh[SEQ*DM], g_avl[SEQ*DM];
__device__ float g_attnout[SEQ*DM];
__device__ bf16 g_ffh[(size_t)SEQ*DFF], g_ffl[(size_t)SEQ*DFF];
__device__ bf16 g_wqth[(size_t)DM*DM],  g_wqtl[(size_t)DM*DM];
__device__ bf16 g_wkth[(size_t)DM*DM],  g_wktl[(size_t)DM*DM];
__device__ bf16 g_wvth[(size_t)DM*DM],  g_wvtl[(size_t)DM*DM];
__device__ bf16 g_woth[(size_t)DM*DM],  g_wotl[(size_t)DM*DM];
__device__ bf16 g_w1th[(size_t)DFF*DM], g_w1tl[(size_t)DFF*DM];
__device__ bf16 g_w2th[(size_t)DM*DFF], g_w2tl[(size_t)DM*DFF];

// ---------------------------------------------------------------------------
// PTX helpers
// ---------------------------------------------------------------------------
__device__ __forceinline__ uint32_t smem_u32(const void* p) {
    uint32_t r;
    asm("{ .reg .u64 t; cvta.to.shared.u64 t, %1; cvt.u32.u64 %0, t; }" : "=r"(r) : "l"(p));
    return r;
}
__device__ __forceinline__ void cp16(uint32_t dst, const void* src) {
    asm volatile("cp.async.cg.shared.global [%0], [%1], 16;" :: "r"(dst), "l"(src));
}
#define CP_COMMIT() asm volatile("cp.async.commit_group;")
#define CP_WAIT(n)  asm volatile("cp.async.wait_group %0;" :: "n"(n))

#define LDMX4(r, a) \
    asm volatile("ldmatrix.sync.aligned.m8n8.x4.shared.b16 {%0,%1,%2,%3}, [%4];" \
        : "=r"((r)[0]), "=r"((r)[1]), "=r"((r)[2]), "=r"((r)[3]) : "r"(a))

#define MMA16816(c, a, b) \
    asm volatile("mma.sync.aligned.m16n8k16.row.col.f32.bf16.bf16.f32 " \
        "{%0,%1,%2,%3}, {%4,%5,%6,%7}, {%8,%9}, {%0,%1,%2,%3};" \
        : "+f"((c)[0]), "+f"((c)[1]), "+f"((c)[2]), "+f"((c)[3]) \
        : "r"((a)[0]), "r"((a)[1]), "r"((a)[2]), "r"((a)[3]), \
          "r"((b)[0]), "r"((b)[1]))

__device__ __forceinline__ void split_store(float v, bf16* ph, bf16* pl, size_t idx) {
    bf16 h = __float2bfloat16(v);
    ph[idx] = h;
    pl[idx] = __float2bfloat16(v - __bfloat162float(h));
}

// Epilogues
#define EPI_F32       0
#define EPI_SCALE     1
#define EPI_HILO      2
#define EPI_GELU_HILO 3
#define EPI_BIAS_ADD  4
// Causal modes
#define CM_NONE   0
#define CM_LOGITS 1   // skip CTA tiles fully above causal diagonal
#define CM_AV     2   // variable K: K_eff = bm + BM

__device__ __forceinline__ float gelu_tanh(float v) {
    const float c = 0.7978845608028654f;
    float t = tanhf(c * (v + 0.044715f * v * v * v));
    return 0.5f * v * (1.0f + t);
}

// ---------------------------------------------------------------------------
// Split-bf16 tensor-core GEMM: C[M,N] = A @ B^T
// A[M,K] row-major hi/lo bf16; B[N,K] row-major hi/lo bf16; fp32 accumulate.
// CTA 128x256, 8 warps, warp tile 64x64, BK=64 double buffered.
// ---------------------------------------------------------------------------
__global__ void __launch_bounds__(256, 1) gemm_bf16x3(
    const bf16* __restrict__ Ah, const bf16* __restrict__ Al, int lda, unsigned long long sA,
    const bf16* __restrict__ Bh, const bf16* __restrict__ Bl, int ldb, unsigned long long sB,
    int K, int epi, int cmode,
    float* __restrict__ Cf, bf16* __restrict__ Ch, bf16* __restrict__ Cl,
    int ldc, unsigned long long sC,
    const float* __restrict__ bias, const float* __restrict__ addv, float scale)
{
    int bm = blockIdx.y * BM;
    int bn = blockIdx.x * BN;
    if (cmode == CM_LOGITS && bn >= bm + BM) return;   // fully causal-masked tile

    extern __shared__ char smem[];
    uint32_t sb = smem_u32(smem);
    int tid = threadIdx.x;
    int wid = tid >> 5, lane = tid & 31;
    int warp_m = wid >> 2, warp_n = wid & 3;

    Ah += (size_t)blockIdx.z * sA;  Al += (size_t)blockIdx.z * sA;
    Bh += (size_t)blockIdx.z * sB;  Bl += (size_t)blockIdx.z * sB;
    size_t coff = (size_t)blockIdx.z * sC;

    // ldmatrix per-lane geometry
    int a_r  = ((lane >> 3) & 1) * 8 + (lane & 7);
    int a_cb = (lane >> 4) * 16;
    int b_r  = (lane >> 4) * 8 + (lane & 7);
    int b_cb = ((lane >> 3) & 1) * 16;

    float acc[4][8][4];
    #pragma unroll
    for (int i = 0; i < 4; i++)
        #pragma unroll
        for (int j = 0; j < 8; j++)
            #pragma unroll
            for (int e = 0; e < 4; e++) acc[i][j][e] = 0.f;

#define LOAD_CHUNK(k0, bufb) do {                                              \
        _Pragma("unroll")                                                      \
        for (int t = 0; t < 4; t++) {                                          \
            int ch = tid + t * 256;                                            \
            int row = ch >> 3, c = ch & 7;                                     \
            uint32_t off = row * 128 + ((c * 16) ^ ((row * 16) & 0x70));       \
            cp16((bufb) + off,            Ah + (size_t)(bm + row) * lda + (k0) + c * 8); \
            cp16((bufb) + A_TILE_B + off, Al + (size_t)(bm + row) * lda + (k0) + c * 8); \
        }                                                                      \
        _Pragma("unroll")                                                      \
        for (int t = 0; t < 8; t++) {                                          \
            int ch = tid + t * 256;                                            \
            int row = ch >> 3, c = ch & 7;                                     \
            uint32_t off = row * 128 + ((c * 16) ^ ((row * 16) & 0x70));       \
            cp16((bufb) + 2*A_TILE_B + off,            Bh + (size_t)(bn + row) * ldb + (k0) + c * 8); \
            cp16((bufb) + 2*A_TILE_B + B_TILE_B + off, Bl + (size_t)(bn + row) * ldb + (k0) + c * 8); \
        }                                                                      \
    } while (0)

    int Keff = (cmode == CM_AV) ? (bm + BM) : K;
    int nk = Keff / BK;

    LOAD_CHUNK(0, sb);
    CP_COMMIT();

    for (int i = 0; i < nk; i++) {
        uint32_t bufb = sb + (uint32_t)(i & 1) * BUF_B;
        if (i + 1 < nk) {
            uint32_t nb = sb + (uint32_t)((i + 1) & 1) * BUF_B;
            LOAD_CHUNK((i + 1) * BK, nb);
            CP_COMMIT();
            CP_WAIT(1);
        } else {
            CP_WAIT(0);
        }
        __syncthreads();

        #pragma unroll
        for (int ks = 0; ks < 4; ks++) {
            uint32_t ahf[4][4], alf[4][4];
            #pragma unroll
            for (int mt = 0; mt < 4; mt++) {
                int row = warp_m * 64 + mt * 16 + a_r;
                uint32_t cb = ks * 32 + a_cb;
                uint32_t off = row * 128 + (cb ^ ((row * 16) & 0x70));
                LDMX4(ahf[mt], bufb + off);
                LDMX4(alf[mt], bufb + A_TILE_B + off);
            }
            uint32_t bhf[8][2], blf[8][2];
            #pragma unroll
            for (int p = 0; p < 4; p++) {
                int row = warp_n * 64 + p * 16 + b_r;
                uint32_t cb = ks * 32 + b_cb;
                uint32_t off = row * 128 + (cb ^ ((row * 16) & 0x70));
                uint32_t r[4];
                LDMX4(r, bufb + 2 * A_TILE_B + off);
                bhf[2*p][0] = r[0]; bhf[2*p][1] = r[1];
                bhf[2*p+1][0] = r[2]; bhf[2*p+1][1] = r[3];
                LDMX4(r, bufb + 2 * A_TILE_B + B_TILE_B + off);
                blf[2*p][0] = r[0]; blf[2*p][1] = r[1];
                blf[2*p+1][0] = r[2]; blf[2*p+1][1] = r[3];
            }
            #pragma unroll
            for (int mt = 0; mt < 4; mt++)
                #pragma unroll
                for (int nt = 0; nt < 8; nt++) {
                    MMA16816(acc[mt][nt], ahf[mt], bhf[nt]);
                    MMA16816(acc[mt][nt], ahf[mt], blf[nt]);
                    MMA16816(acc[mt][nt], alf[mt], bhf[nt]);
                }
        }
        __syncthreads();
    }
#undef LOAD_CHUNK

    // Epilogue: direct global stores (2 fp32 per quad-lane per sub-tile half)
    int g = lane >> 2, tg = lane & 3;
    #pragma unroll
    for (int mt = 0; mt < 4; mt++) {
        #pragma unroll
        for (int nt = 0; nt < 8; nt++) {
            int row0 = bm + warp_m * 64 + mt * 16 + g;
            int col  = bn + warp_n * 64 + nt * 8 + tg * 2;
            float* a = acc[mt][nt];
            #pragma unroll
            for (int half = 0; half < 2; half++) {
                int row = row0 + half * 8;
                float v0 = a[half * 2 + 0], v1 = a[half * 2 + 1];
                size_t idx = coff + (size_t)row * ldc + col;
                if (epi == EPI_F32) {
                    *(float2*)(Cf + idx) = make_float2(v0, v1);
                } else if (epi == EPI_SCALE) {
                    *(float2*)(Cf + idx) = make_float2(v0 * scale, v1 * scale);
                } else if (epi == EPI_HILO) {
                    bf16 h0 = __float2bfloat16(v0), h1 = __float2bfloat16(v1);
                    __nv_bfloat162 hp; hp.x = h0; hp.y = h1;
                    __nv_bfloat162 lp;
                    lp.x = __float2bfloat16(v0 - __bfloat162float(h0));
                    lp.y = __float2bfloat16(v1 - __bfloat162float(h1));
                    *(__nv_bfloat162*)(Ch + idx) = hp;
                    *(__nv_bfloat162*)(Cl + idx) = lp;
                } else if (epi == EPI_GELU_HILO) {
                    float g0 = gelu_tanh(v0 + bias[col]);
                    float g1 = gelu_tanh(v1 + bias[col + 1]);
                    bf16 h0 = __float2bfloat16(g0), h1 = __float2bfloat16(g1);
                    __nv_bfloat162 hp; hp.x = h0; hp.y = h1;
                    __nv_bfloat162 lp;
                    lp.x = __float2bfloat16(g0 - __bfloat162float(h0));
                    lp.y = __float2bfloat16(g1 - __bfloat162float(h1));
                    *(__nv_bfloat162*)(Ch + idx) = hp;
                    *(__nv_bfloat162*)(Cl + idx) = lp;
                } else { // EPI_BIAS_ADD
                    float2 av = *(const float2*)(addv + idx);
                    *(float2*)(Cf + idx) = make_float2(v0 + bias[col] + av.x,
                                                       v1 + bias[col + 1] + av.y);
                }
            }
        }
    }
}

// ---------------------------------------------------------------------------
// LayerNorm -> hi/lo bf16
// ---------------------------------------------------------------------------
__global__ void ln_kernel(const float* __restrict__ x,
                          const float* __restrict__ scale,
                          const float* __restrict__ offset,
                          bf16* __restrict__ xh, bf16* __restrict__ xl)
{
    __shared__ float red[256];
    int row = blockIdx.x;
    int tid = threadIdx.x;
    const float* xr = x + (size_t)row * DM;

    float s = 0.f;
    for (int i = tid; i < DM; i += 256) s += xr[i];
    red[tid] = s; __syncthreads();
    for (int o = 128; o > 0; o >>= 1) { if (tid < o) red[tid] += red[tid + o]; __syncthreads(); }
    float mean = red[0] / (float)DM;
    __syncthreads();

    float v = 0.f;
    for (int i = tid; i < DM; i += 256) { float d = xr[i] - mean; v += d * d; }
    red[tid] = v; __syncthreads();
    for (int o = 128; o > 0; o >>= 1) { if (tid < o) red[tid] += red[tid + o]; __syncthreads(); }
    float r = rsqrtf(red[0] / (float)DM + 1e-5f);

    for (int i = tid; i < DM; i += 256) {
        float y = scale[i] * r * (xr[i] - mean) + offset[i];
        split_store(y, xh, xl, (size_t)row * DM + i);
    }
}

// ---------------------------------------------------------------------------
// Transpose + hi/lo convert: in[R][C] fp32 -> out[C][R] hi/lo bf16
// ---------------------------------------------------------------------------
__global__ void transcvt_kernel(const float* __restrict__ in, int R, int C,
                                bf16* __restrict__ oh, bf16* __restrict__ ol)
{
    __shared__ float t[32][33];
    int c0 = blockIdx.x * 32;
    int r0 = blockIdx.y * 32;
    int tx = threadIdx.x, ty = threadIdx.y;  // (32,8)
    #pragma unroll
    for (int j = 0; j < 32; j += 8)
        t[ty + j][tx] = in[(size_t)(r0 + ty + j) * C + c0 + tx];
    __syncthreads();
    #pragma unroll
    for (int j = 0; j < 32; j += 8) {
        float v = t[tx][ty + j];
        split_store(v, oh, ol, (size_t)(c0 + ty + j) * R + r0 + tx);
    }
}

// ---------------------------------------------------------------------------
// RoPE (fp64 angles, first 64 dims per head) + hi/lo convert of full q,k
// ---------------------------------------------------------------------------
__global__ void rope_cvt_kernel(const float* __restrict__ q, const float* __restrict__ k,
                                bf16* __restrict__ qh, bf16* __restrict__ ql,
                                bf16* __restrict__ kh, bf16* __restrict__ kl)
{
    int idx = blockIdx.x * 256 + threadIdx.x;
    if (idx >= SEQ * NH * 128) return;
    int p = idx & 127;
    int h = (idx >> 7) & (NH - 1);
    int t = idx >> 11;
    size_t base = (size_t)t * DM + (size_t)h * DH + 2 * p;
    float q0 = q[base], q1 = q[base + 1];
    float k0 = k[base], k1 = k[base + 1];
    if (p < 32) {
        double inv = exp(-(double)p * (9.210340371976184 / 32.0));
        double ds, dc;
        sincos((double)t * inv, &ds, &dc);
        float s = (float)ds, c = (float)dc;
        float a = q0 * c - q1 * s, b = q1 * c + q0 * s; q0 = a; q1 = b;
        a = k0 * c - k1 * s; b = k1 * c + k0 * s; k0 = a; k1 = b;
    }
    split_store(q0, qh, ql, base);
    split_store(q1, qh, ql, base + 1);
    split_store(k0, kh, kl, base);
    split_store(k1, kh, kl, base + 1);
}

// ---------------------------------------------------------------------------
// Causal softmax v2: cache row in smem (1 global read), zero-fill only to
// the 128-row block end (AV GEMM uses variable K = blockend).
// ---------------------------------------------------------------------------
__global__ void softmax_kernel(const float* __restrict__ logits,
                               const float* __restrict__ attn_bias,
                               bf16* __restrict__ wh, bf16* __restrict__ wl)
{
    __shared__ float rowbuf[SEQ];
    __shared__ float red[256];
    int t = blockIdx.x;
    int h = blockIdx.y;
    int tid = threadIdx.x;
    size_t base = ((size_t)h * SEQ + t) * SEQ;
    const float* brow = attn_bias + (size_t)t * SEQ;
    int n = t + 1;
    int blockend = ((t >> 7) + 1) << 7;

    float m = -INFINITY;
    for (int T = tid; T < n; T += 256) {
        float l = logits[base + T] + brow[T];
        rowbuf[T] = l;
        m = fmaxf(m, l);
    }
    red[tid] = m; __syncthreads();
    for (int o = 128; o > 0; o >>= 1) { if (tid < o) red[tid] = fmaxf(red[tid], red[tid + o]); __syncthreads(); }
    m = red[0]; __syncthreads();

    float s = 0.f;
    for (int T = tid; T < n; T += 256) {
        float e = expf(rowbuf[T] - m);
        rowbuf[T] = e;
        s += e;
    }
    red[tid] = s; __syncthreads();
    for (int o = 128; o > 0; o >>= 1) { if (tid < o) red[tid] += red[tid + o]; __syncthreads(); }
    float inv = 1.0f / red[0];

    for (int T = tid; T < n; T += 256)
        split_store(rowbuf[T] * inv, wh, wl, base + T);
    for (int T = n + tid; T < blockend; T += 256) {
        wh[base + T] = __float2bfloat16(0.f);
        wl[base + T] = __float2bfloat16(0.f);
    }
}

// ---------------------------------------------------------------------------
// Launcher
// ---------------------------------------------------------------------------
extern "C" void kernel_launch(void* const* d_in, const int* in_sizes, int n_in,
                              void* d_out, int out_size)
{
    const float* x         = (const float*)d_in[0];
    const float* attn_bias = (const float*)d_in[1];
    const float* ln_scale  = (const float*)d_in[2];
    const float* ln_offset = (const float*)d_in[3];
    const float* wq        = (const float*)d_in[4];
    const float* wk        = (const float*)d_in[5];
    const float* wv        = (const float*)d_in[6];
    const float* wo        = (const float*)d_in[7];
    const float* w1        = (const float*)d_in[8];
    const float* b1        = (const float*)d_in[9];
    const float* w2        = (const float*)d_in[10];
    const float* b2        = (const float*)d_in[11];
    float* out = (float*)d_out;

    cudaFuncSetAttribute(gemm_bf16x3, cudaFuncAttributeMaxDynamicSharedMemorySize, GEMM_SMEM);

    bf16 *xnh, *xnl, *qh, *ql, *kh, *kl, *vth, *vtl, *wgh, *wgl, *avh, *avl, *ffh, *ffl;
    bf16 *wqth, *wqtl, *wkth, *wktl, *wvth, *wvtl, *woth, *wotl, *w1th, *w1tl, *w2th, *w2tl;
    float *q, *k, *v, *logits, *attnout;
    cudaGetSymbolAddress((void**)&xnh, g_xnh);   cudaGetSymbolAddress((void**)&xnl, g_xnl);
    cudaGetSymbolAddress((void**)&q, g_q);       cudaGetSymbolAddress((void**)&k, g_k);
    cudaGetSymbolAddress((void**)&v, g_v);
    cudaGetSymbolAddress((void**)&qh, g_qh);     cudaGetSymbolAddress((void**)&ql, g_ql);
    cudaGetSymbolAddress((void**)&kh, g_kh);     cudaGetSymbolAddress((void**)&kl, g_kl);
    cudaGetSymbolAddress((void**)&vth, g_vth);   cudaGetSymbolAddress((void**)&vtl, g_vtl);
    cudaGetSymbolAddress((void**)&logits, g_logits);
    cudaGetSymbolAddress((void**)&wgh, g_wgh);   cudaGetSymbolAddress((void**)&wgl, g_wgl);
    cudaGetSymbolAddress((void**)&avh, g_avh);   cudaGetSymbolAddress((void**)&avl, g_avl);
    cudaGetSymbolAddress((void**)&attnout, g_attnout);
    cudaGetSymbolAddress((void**)&ffh, g_ffh);   cudaGetSymbolAddress((void**)&ffl, g_ffl);
    cudaGetSymbolAddress((void**)&wqth, g_wqth); cudaGetSymbolAddress((void**)&wqtl, g_wqtl);
    cudaGetSymbolAddress((void**)&wkth, g_wkth); cudaGetSymbolAddress((void**)&wktl, g_wktl);
    cudaGetSymbolAddress((void**)&wvth, g_wvth); cudaGetSymbolAddress((void**)&wvtl, g_wvtl);
    cudaGetSymbolAddress((void**)&woth, g_woth); cudaGetSymbolAddress((void**)&wotl, g_wotl);
    cudaGetSymbolAddress((void**)&w1th, g_w1th); cudaGetSymbolAddress((void**)&w1tl, g_w1tl);
    cudaGetSymbolAddress((void**)&w2th, g_w2th); cudaGetSymbolAddress((void**)&w2tl, g_w2tl);

    dim3 tb(32, 8);
    transcvt_kernel<<<dim3(DM / 32, DM / 32), tb>>>(wq, DM, DM, wqth, wqtl);
    transcvt_kernel<<<dim3(DM / 32, DM / 32), tb>>>(wk, DM, DM, wkth, wktl);
    transcvt_kernel<<<dim3(DM / 32, DM / 32), tb>>>(wv, DM, DM, wvth, wvtl);
    transcvt_kernel<<<dim3(DM / 32, DM / 32), tb>>>(wo, DM, DM, woth, wotl);
    transcvt_kernel<<<dim3(DFF / 32, DM / 32), tb>>>(w1, DM, DFF, w1th, w1tl);
    transcvt_kernel<<<dim3(DM / 32, DFF / 32), tb>>>(w2, DFF, DM, w2th, w2tl);

    ln_kernel<<<SEQ, 256>>>(x, ln_scale, ln_offset, xnh, xnl);

    dim3 gProj(DM / BN, SEQ / BM, 1);
    gemm_bf16x3<<<gProj, 256, GEMM_SMEM>>>(xnh, xnl, DM, 0, wqth, wqtl, DM, 0, DM,
                                           EPI_F32, CM_NONE, q, nullptr, nullptr, DM, 0, nullptr, nullptr, 1.f);
    gemm_bf16x3<<<gProj, 256, GEMM_SMEM>>>(xnh, xnl, DM, 0, wkth, wktl, DM, 0, DM,
                                           EPI_F32, CM_NONE, k, nullptr, nullptr, DM, 0, nullptr, nullptr, 1.f);
    gemm_bf16x3<<<gProj, 256, GEMM_SMEM>>>(xnh, xnl, DM, 0, wvth, wvtl, DM, 0, DM,
                                           EPI_F32, CM_NONE, v, nullptr, nullptr, DM, 0, nullptr, nullptr, 1.f);

    rope_cvt_kernel<<<(SEQ * NH * 128 + 255) / 256, 256>>>(q, k, qh, ql, kh, kl);

    transcvt_kernel<<<dim3(DM / 32, SEQ / 32), tb>>>(v, SEQ, DM, vth, vtl);

    // logits[h] = q_h @ k_h^T / 16 (skip fully masked tiles)
    dim3 gLog(SEQ / BN, SEQ / BM, NH);
    gemm_bf16x3<<<gLog, 256, GEMM_SMEM>>>(qh, ql, DM, DH, kh, kl, DM, DH, DH,
                                          EPI_SCALE, CM_LOGITS, logits, nullptr, nullptr, SEQ, (unsigned long long)SEQ * SEQ,
                                          nullptr, nullptr, 0.0625f);

    softmax_kernel<<<dim3(SEQ, NH), 256>>>(logits, attn_bias, wgh, wgl);

    // attn_vec[h] = W_h @ v_h  (variable K = row block end)
    dim3 gAV(DH / BN, SEQ / BM, NH);
    gemm_bf16x3<<<gAV, 256, GEMM_SMEM>>>(wgh, wgl, SEQ, (unsigned long long)SEQ * SEQ,
                                         vth, vtl, SEQ, (unsigned long long)DH * SEQ, SEQ,
                                         EPI_HILO, CM_AV, nullptr, avh, avl, DM, DH, nullptr, nullptr, 1.f);

    gemm_bf16x3<<<gProj, 256, GEMM_SMEM>>>(avh, avl, DM, 0, woth, wotl, DM, 0, DM,
                                           EPI_F32, CM_NONE, attnout, nullptr, nullptr, DM, 0, nullptr, nullptr, 1.f);

    dim3 gFF1(DFF / BN, SEQ / BM, 1);
    gemm_bf16x3<<<gFF1, 256, GEMM_SMEM>>>(xnh, xnl, DM, 0, w1th, w1tl, DM, 0, DM,
                                          EPI_GELU_HILO, CM_NONE, nullptr, ffh, ffl, DFF, 0, b1, nullptr, 1.f);

    dim3 gFF2(DM / BN, SEQ / BM, 1);
    gemm_bf16x3<<<gFF2, 256, GEMM_SMEM>>>(ffh, ffl, DFF, 0, w2th, w2tl, DFF, 0, DFF,
                                          EPI_BIAS_ADD, CM_NONE, out, nullptr, nullptr, DM, 0, b2, attnout, 1.f);
}